// round 1
// baseline (speedup 1.0000x reference)
#include <cuda_runtime.h>
#include <math.h>

// Problem constants
#define TT 1024
#define BB 32
#define II 512
#define HH 512
#define G4 2048  // 4*H

// Output layout (flattened tuple, in reference return order)
#define OUT_OUTPUT 0u
#define OUT_HT     16777216u                 // T*B*H
#define OUT_CT     (16777216u + 16384u)
#define OUT_ALLH   (16777216u + 32768u)

// ---------------- device scratch (no allocations allowed) ----------------
__device__ float g_Gx[(size_t)TT * BB * G4];   // 268 MB precomputed x-projection
__device__ float g_hbuf[2][BB * HH];           // double-buffered recurrent state h
__device__ unsigned int g_bar_count = 0;       // monotonic arrive counter
__device__ unsigned int g_bar_gen   = 0;       // barrier generation

// =========================================================================
// Phase A: Gx[m][n] = dot(x[m,:], Wx[n,:]) + b[n]
// M=32768, N=2048, K=512.  128x128 tile, BK=8, 256 threads, 8x8 microtile.
// =========================================================================
__global__ __launch_bounds__(256, 2) void gemm_gx(const float* __restrict__ X,
                                                  const float* __restrict__ Wx,
                                                  const float* __restrict__ bias)
{
    __shared__ float As[8][132];
    __shared__ float Bs[8][132];

    const int tid = threadIdx.x;
    const int tx = tid & 15;
    const int ty = tid >> 4;
    const int m0 = blockIdx.y * 128;
    const int n0 = blockIdx.x * 128;

    const int lr = tid >> 1;   // tile row for the cooperative load (0..127)
    const int lq = tid & 1;    // which float4 of the 8-wide K chunk

    const float* agp = X  + (size_t)(m0 + lr) * 512 + lq * 4;
    const float* bgp = Wx + (size_t)(n0 + lr) * 512 + lq * 4;

    float acc[8][8];
#pragma unroll
    for (int i = 0; i < 8; i++)
#pragma unroll
        for (int j = 0; j < 8; j++) acc[i][j] = 0.f;

    for (int kb = 0; kb < 512; kb += 8) {
        float4 av = *(const float4*)(agp + kb);
        float4 bv = *(const float4*)(bgp + kb);
        __syncthreads();
        As[lq * 4 + 0][lr] = av.x; As[lq * 4 + 1][lr] = av.y;
        As[lq * 4 + 2][lr] = av.z; As[lq * 4 + 3][lr] = av.w;
        Bs[lq * 4 + 0][lr] = bv.x; Bs[lq * 4 + 1][lr] = bv.y;
        Bs[lq * 4 + 2][lr] = bv.z; Bs[lq * 4 + 3][lr] = bv.w;
        __syncthreads();
#pragma unroll
        for (int k = 0; k < 8; k++) {
            float a[8], b[8];
            *(float4*)(a)     = *(const float4*)&As[k][ty * 4];
            *(float4*)(a + 4) = *(const float4*)&As[k][64 + ty * 4];
            *(float4*)(b)     = *(const float4*)&Bs[k][tx * 4];
            *(float4*)(b + 4) = *(const float4*)&Bs[k][64 + tx * 4];
#pragma unroll
            for (int i = 0; i < 8; i++)
#pragma unroll
                for (int j = 0; j < 8; j++)
                    acc[i][j] += a[i] * b[j];
        }
    }

    // Epilogue: rows {m0+ty*4+i, m0+64+ty*4+i}, cols {n0+tx*4.., n0+64+tx*4..}
#pragma unroll
    for (int i = 0; i < 8; i++) {
        int m = m0 + ((i < 4) ? (ty * 4 + i) : (64 + ty * 4 + (i - 4)));
        float* dst = g_Gx + (size_t)m * 2048;
        int n1 = n0 + tx * 4;
        int n2 = n0 + 64 + tx * 4;
        float4 v1, v2;
        v1.x = acc[i][0] + bias[n1 + 0];
        v1.y = acc[i][1] + bias[n1 + 1];
        v1.z = acc[i][2] + bias[n1 + 2];
        v1.w = acc[i][3] + bias[n1 + 3];
        v2.x = acc[i][4] + bias[n2 + 0];
        v2.y = acc[i][5] + bias[n2 + 1];
        v2.z = acc[i][6] + bias[n2 + 2];
        v2.w = acc[i][7] + bias[n2 + 3];
        *(float4*)(dst + n1) = v1;
        *(float4*)(dst + n2) = v2;
    }
}

// =========================================================================
// Phase B: persistent recurrent kernel. 128 blocks x 256 threads.
// Block bid owns hidden columns j = bid*4 .. bid*4+3 and ALL 4 gates for
// them (16 Wh rows), so the nonlinearity is block-local -> 1 grid barrier
// per timestep.  h is double-buffered in global; Wh tile persists in smem.
//
// smem layout (floats):
//   h_s : [32][516]  (padded rows; conflict-free)          0     .. 16511
//   wh_s: [16][516]  row order srow = gate*4 + jj          16512 .. 24767
//   red : [256][16]  split-K partials                      24768 .. 28863
// total = 28864 floats = 115456 B  -> 1 CTA/SM, all 128 CTAs resident.
// =========================================================================
#define SMEM_FLOATS 28864
#define SMEM_BYTES  (SMEM_FLOATS * 4)

#define FMA4(A, W, Hv) { A += (W).x*(Hv).x; A += (W).y*(Hv).y; A += (W).z*(Hv).z; A += (W).w*(Hv).w; }

__global__ __launch_bounds__(256, 1) void lstm_seq(
    const float* __restrict__ h0,
    const float* __restrict__ c0,
    const float* __restrict__ Wh,
    float* __restrict__ out)
{
    extern __shared__ float sm[];
    float* h_s  = sm;
    float* wh_s = sm + 16512;
    float* red  = sm + 24768;

    const int tid = threadIdx.x;
    const int bid = blockIdx.x;
    const int j0  = bid * 4;

    // Load this block's 16 Wh rows once (row srow = g*4 + jj  <->  Wh[g*512 + j0 + jj])
    for (int i = tid; i < 2048; i += 256) {
        int srow = i >> 7;            // 128 float4 per row
        int q    = i & 127;
        int g    = srow >> 2;
        int jj2  = srow & 3;
        *(float4*)(wh_s + srow * 516 + q * 4) =
            *(const float4*)(Wh + (size_t)(g * 512 + j0 + jj2) * 512 + q * 4);
    }

    // Main-loop decomposition: kseg = warp (k range of 64), slot = lane
    const int kseg = tid >> 5;        // 0..7
    const int slot = tid & 31;
    const int bg   = slot >> 2;       // 0..7 -> batches bg*4..bg*4+3
    const int jj   = slot & 3;        // 0..3 -> this thread's hidden col

    // Elementwise / state stage mapping (tid < 128): one (b, jj) pair
    const int fb  = tid >> 2;         // 0..31
    const int fjj = tid & 3;
    float c_reg = (tid < 128) ? c0[fb * 512 + j0 + fjj] : 0.f;

    const float4* wrow0 = (const float4*)(wh_s + (0  + jj) * 516);
    const float4* wrow1 = (const float4*)(wh_s + (4  + jj) * 516);
    const float4* wrow2 = (const float4*)(wh_s + (8  + jj) * 516);
    const float4* wrow3 = (const float4*)(wh_s + (12 + jj) * 516);
    const float4* hrow0 = (const float4*)(h_s + (bg * 4 + 0) * 516);
    const float4* hrow1 = (const float4*)(h_s + (bg * 4 + 1) * 516);
    const float4* hrow2 = (const float4*)(h_s + (bg * 4 + 2) * 516);
    const float4* hrow3 = (const float4*)(h_s + (bg * 4 + 3) * 516);

    for (int t = 0; t < TT; t++) {
        // Stage h_{t-1} into smem (padded rows)
        const float* hsrc = (t == 0) ? h0 : g_hbuf[t & 1];
        for (int i = tid; i < 4096; i += 256) {
            int b = i >> 7, q = i & 127;
            *(float4*)(h_s + b * 516 + q * 4) = *(const float4*)(hsrc + b * 512 + q * 4);
        }
        __syncthreads();

        // Split-K partial dot products: acc[gate][bb] over k = kseg*64 .. +63
        float acc[4][4];
#pragma unroll
        for (int g = 0; g < 4; g++)
#pragma unroll
            for (int b = 0; b < 4; b++) acc[g][b] = 0.f;

        int k4 = kseg * 16;
#pragma unroll 8
        for (int kc = 0; kc < 16; kc++, k4++) {
            float4 w0 = wrow0[k4], w1 = wrow1[k4], w2 = wrow2[k4], w3 = wrow3[k4];
            float4 hv0 = hrow0[k4], hv1 = hrow1[k4], hv2 = hrow2[k4], hv3 = hrow3[k4];
            FMA4(acc[0][0], w0, hv0) FMA4(acc[0][1], w0, hv1) FMA4(acc[0][2], w0, hv2) FMA4(acc[0][3], w0, hv3)
            FMA4(acc[1][0], w1, hv0) FMA4(acc[1][1], w1, hv1) FMA4(acc[1][2], w1, hv2) FMA4(acc[1][3], w1, hv3)
            FMA4(acc[2][0], w2, hv0) FMA4(acc[2][1], w2, hv1) FMA4(acc[2][2], w2, hv2) FMA4(acc[2][3], w2, hv3)
            FMA4(acc[3][0], w3, hv0) FMA4(acc[3][1], w3, hv1) FMA4(acc[3][2], w3, hv2) FMA4(acc[3][3], w3, hv3)
        }

        float* rp = red + tid * 16;
#pragma unroll
        for (int g = 0; g < 4; g++)
#pragma unroll
            for (int b = 0; b < 4; b++)
                rp[g * 4 + b] = acc[g][b];
        __syncthreads();

        // Reduce across the 8 k-segments, add Gx, apply gates, update state
        if (tid < 128) {
            const int bgf = fb >> 2, bbf = fb & 3;
            const float* gx = g_Gx + (size_t)t * 65536 + (size_t)fb * 2048 + j0 + fjj;
            float gates[4];
#pragma unroll
            for (int g = 0; g < 4; g++) {
                float s = gx[g * 512];
#pragma unroll
                for (int ks = 0; ks < 8; ks++)
                    s += red[(ks * 32 + bgf * 4 + fjj) * 16 + g * 4 + bbf];
                gates[g] = s;
            }
            float gi = 1.f / (1.f + __expf(-gates[0]));
            float gf = 1.f / (1.f + __expf(-gates[1]));
            float gg = tanhf(gates[2]);
            float go = 1.f / (1.f + __expf(-gates[3]));
            float cn = gf * c_reg + gi * gg;
            float hn = go * tanhf(cn);
            c_reg = cn;

            const int j = j0 + fjj;
            g_hbuf[(t + 1) & 1][fb * 512 + j] = hn;
            size_t off = (size_t)t * 16384 + (size_t)fb * 512 + j;
            out[OUT_OUTPUT + off] = hn;
            out[OUT_ALLH   + off] = hn;
            if (t == TT - 1) {
                out[OUT_HT + fb * 512 + j] = hn;
                out[OUT_CT + fb * 512 + j] = cn;
            }
        }

        // ---- grid-wide barrier (monotonic count, generation flag) ----
        __syncthreads();
        if (tid == 0) {
            __threadfence();  // publish h / out writes
            unsigned int gen = *(volatile unsigned int*)&g_bar_gen;
            __threadfence();
            unsigned int arrive = atomicAdd(&g_bar_count, 1);
            if ((arrive & 127u) == 127u) {
                __threadfence();
                atomicAdd(&g_bar_gen, 1);
            } else {
                while (*(volatile unsigned int*)&g_bar_gen == gen) { }
            }
            __threadfence();  // acquire
        }
        __syncthreads();
    }
}

// =========================================================================
extern "C" void kernel_launch(void* const* d_in, const int* in_sizes, int n_in,
                              void* d_out, int out_size)
{
    const float* x    = (const float*)d_in[0];
    const float* h0   = (const float*)d_in[1];
    const float* c0   = (const float*)d_in[2];
    const float* Wx   = (const float*)d_in[3];
    const float* Wh   = (const float*)d_in[4];
    const float* bias = (const float*)d_in[5];
    float* out = (float*)d_out;

    dim3 gridA(16, 256);           // N tiles x M tiles
    gemm_gx<<<gridA, 256>>>(x, Wx, bias);

    cudaFuncSetAttribute(lstm_seq, cudaFuncAttributeMaxDynamicSharedMemorySize, SMEM_BYTES);
    lstm_seq<<<128, 256, SMEM_BYTES>>>(h0, c0, Wh, out);
}

// round 2
// speedup vs baseline: 1.1160x; 1.1160x over previous
#include <cuda_runtime.h>
#include <math.h>

// Problem constants
#define TT 1024
#define BB 32
#define II 512
#define HH 512
#define G4 2048  // 4*H

// Output layout (flattened tuple, in reference return order)
#define OUT_OUTPUT 0u
#define OUT_HT     16777216u                 // T*B*H
#define OUT_CT     (16777216u + 16384u)
#define OUT_ALLH   (16777216u + 32768u)

// ---------------- device scratch (no allocations allowed) ----------------
__device__ float g_Gx[(size_t)TT * BB * G4];   // 268 MB precomputed x-projection
__device__ float g_hbuf[2][BB * HH];           // double-buffered recurrent state h
__device__ unsigned int g_flags[128 * 32];     // per-block arrival flag, 128B padded
__device__ unsigned int g_gen = 0;             // generation (monotonic across replays)

// =========================================================================
// Phase A: Gx[m][n] = dot(x[m,:], Wx[n,:]) + b[n]
// M=32768, N=2048, K=512.  128x128 tile, BK=8, 256 threads, 8x8 microtile.
// =========================================================================
__global__ __launch_bounds__(256, 2) void gemm_gx(const float* __restrict__ X,
                                                  const float* __restrict__ Wx,
                                                  const float* __restrict__ bias)
{
    __shared__ float As[8][132];
    __shared__ float Bs[8][132];

    const int tid = threadIdx.x;
    const int tx = tid & 15;
    const int ty = tid >> 4;
    const int m0 = blockIdx.y * 128;
    const int n0 = blockIdx.x * 128;

    const int lr = tid >> 1;   // tile row for the cooperative load (0..127)
    const int lq = tid & 1;    // which float4 of the 8-wide K chunk

    const float* agp = X  + (size_t)(m0 + lr) * 512 + lq * 4;
    const float* bgp = Wx + (size_t)(n0 + lr) * 512 + lq * 4;

    float acc[8][8];
#pragma unroll
    for (int i = 0; i < 8; i++)
#pragma unroll
        for (int j = 0; j < 8; j++) acc[i][j] = 0.f;

    for (int kb = 0; kb < 512; kb += 8) {
        float4 av = *(const float4*)(agp + kb);
        float4 bv = *(const float4*)(bgp + kb);
        __syncthreads();
        As[lq * 4 + 0][lr] = av.x; As[lq * 4 + 1][lr] = av.y;
        As[lq * 4 + 2][lr] = av.z; As[lq * 4 + 3][lr] = av.w;
        Bs[lq * 4 + 0][lr] = bv.x; Bs[lq * 4 + 1][lr] = bv.y;
        Bs[lq * 4 + 2][lr] = bv.z; Bs[lq * 4 + 3][lr] = bv.w;
        __syncthreads();
#pragma unroll
        for (int k = 0; k < 8; k++) {
            float a[8], b[8];
            *(float4*)(a)     = *(const float4*)&As[k][ty * 4];
            *(float4*)(a + 4) = *(const float4*)&As[k][64 + ty * 4];
            *(float4*)(b)     = *(const float4*)&Bs[k][tx * 4];
            *(float4*)(b + 4) = *(const float4*)&Bs[k][64 + tx * 4];
#pragma unroll
            for (int i = 0; i < 8; i++)
#pragma unroll
                for (int j = 0; j < 8; j++)
                    acc[i][j] += a[i] * b[j];
        }
    }

#pragma unroll
    for (int i = 0; i < 8; i++) {
        int m = m0 + ((i < 4) ? (ty * 4 + i) : (64 + ty * 4 + (i - 4)));
        float* dst = g_Gx + (size_t)m * 2048;
        int n1 = n0 + tx * 4;
        int n2 = n0 + 64 + tx * 4;
        float4 v1, v2;
        v1.x = acc[i][0] + bias[n1 + 0];
        v1.y = acc[i][1] + bias[n1 + 1];
        v1.z = acc[i][2] + bias[n1 + 2];
        v1.w = acc[i][3] + bias[n1 + 3];
        v2.x = acc[i][4] + bias[n2 + 0];
        v2.y = acc[i][5] + bias[n2 + 1];
        v2.z = acc[i][6] + bias[n2 + 2];
        v2.w = acc[i][7] + bias[n2 + 3];
        *(float4*)(dst + n1) = v1;
        *(float4*)(dst + n2) = v2;
    }
}

// =========================================================================
// Phase B: persistent recurrent kernel. 128 blocks x 512 threads.
// Block bid owns hidden columns j = bid*4 .. bid*4+3 and ALL 4 gates for
// them (16 Wh rows).  16-way split-K across warps, shfl-combined finalize,
// flag-array grid barrier (no serialized atomics).
//
// smem layout (floats):
//   h_s : [32][516]                         0     .. 16511
//   wh_s: [16][516]  row srow = gate*4+jj   16512 .. 24767
//   red : [16][521]  (g*4+b major)          24768 .. 33103
// =========================================================================
#define SMEM_FLOATS 33104
#define SMEM_BYTES  (SMEM_FLOATS * 4)

#define FMA4(A, W, Hv) { A += (W).x*(Hv).x; A += (W).y*(Hv).y; A += (W).z*(Hv).z; A += (W).w*(Hv).w; }

__global__ __launch_bounds__(512, 1) void lstm_seq(
    const float* __restrict__ h0,
    const float* __restrict__ c0,
    const float* __restrict__ Wh,
    float* __restrict__ out)
{
    extern __shared__ float sm[];
    float* h_s  = sm;
    float* wh_s = sm + 16512;
    float* red  = sm + 24768;

    const int tid = threadIdx.x;
    const int bid = blockIdx.x;
    const int j0  = bid * 4;

    // Monotonic epoch base: value left in g_gen by the previous replay.
    // No block writes g_gen until all 128 have arrived at barrier 0, and every
    // block reads base before arriving, so all blocks see the same base.
    const unsigned int base = *(volatile unsigned int*)&g_gen;

    // Load this block's 16 Wh rows once (srow = g*4 + jj  <->  Wh[g*512 + j0 + jj])
    for (int i = tid; i < 2048; i += 512) {
        int srow = i >> 7;            // 128 float4 per row
        int q    = i & 127;
        int g    = srow >> 2;
        int jj2  = srow & 3;
        *(float4*)(wh_s + srow * 516 + q * 4) =
            *(const float4*)(Wh + (size_t)(g * 512 + j0 + jj2) * 512 + q * 4);
    }

    // Compute-phase mapping: 16 k-segments (one per warp), 32 k each.
    const int kseg = tid >> 5;        // 0..15
    const int slot = tid & 31;
    const int bg   = slot >> 2;       // batch group 0..7
    const int jj   = slot & 3;        // hidden col within block

    // Finalize mapping: one (batch, col, gate) per thread.
    const int gate = tid & 3;
    const int pair = tid >> 2;        // 0..127
    const int fb   = pair >> 2;       // batch 0..31
    const int fjj  = pair & 3;
    const int bgf  = fb >> 2, bbf = fb & 3;
    float c_reg = c0[fb * 512 + j0 + fjj];   // replicated across the quad

    const float4* wrow0 = (const float4*)(wh_s + (0  + jj) * 516);
    const float4* wrow1 = (const float4*)(wh_s + (4  + jj) * 516);
    const float4* wrow2 = (const float4*)(wh_s + (8  + jj) * 516);
    const float4* wrow3 = (const float4*)(wh_s + (12 + jj) * 516);
    const float4* hrow0 = (const float4*)(h_s + (bg * 4 + 0) * 516);
    const float4* hrow1 = (const float4*)(h_s + (bg * 4 + 1) * 516);
    const float4* hrow2 = (const float4*)(h_s + (bg * 4 + 2) * 516);
    const float4* hrow3 = (const float4*)(h_s + (bg * 4 + 3) * 516);

    const float* rbase = red + (gate * 4 + bbf) * 521 + bgf * 4 + fjj;
    const int lane = tid & 31;
    const int q    = lane & ~3;

    for (int t = 0; t < TT; t++) {
        // Prefetch this thread's Gx element (independent of h)
        float gxv = g_Gx[(size_t)t * 65536 + (size_t)fb * 2048 + gate * 512 + j0 + fjj];

        // Stage h_{t-1} into smem (padded rows)
        const float* hsrc = (t == 0) ? h0 : g_hbuf[t & 1];
        for (int i = tid; i < 4096; i += 512) {
            int b = i >> 7, qq = i & 127;
            *(float4*)(h_s + b * 516 + qq * 4) = *(const float4*)(hsrc + b * 512 + qq * 4);
        }
        __syncthreads();

        // Split-K partials over k = kseg*32 .. +31
        float acc[4][4];
#pragma unroll
        for (int g = 0; g < 4; g++)
#pragma unroll
            for (int b = 0; b < 4; b++) acc[g][b] = 0.f;

        int k4 = kseg * 8;
#pragma unroll
        for (int kc = 0; kc < 8; kc++, k4++) {
            float4 w0 = wrow0[k4], w1 = wrow1[k4], w2 = wrow2[k4], w3 = wrow3[k4];
            float4 hv0 = hrow0[k4], hv1 = hrow1[k4], hv2 = hrow2[k4], hv3 = hrow3[k4];
            FMA4(acc[0][0], w0, hv0) FMA4(acc[0][1], w0, hv1) FMA4(acc[0][2], w0, hv2) FMA4(acc[0][3], w0, hv3)
            FMA4(acc[1][0], w1, hv0) FMA4(acc[1][1], w1, hv1) FMA4(acc[1][2], w1, hv2) FMA4(acc[1][3], w1, hv3)
            FMA4(acc[2][0], w2, hv0) FMA4(acc[2][1], w2, hv1) FMA4(acc[2][2], w2, hv2) FMA4(acc[2][3], w2, hv3)
            FMA4(acc[3][0], w3, hv0) FMA4(acc[3][1], w3, hv1) FMA4(acc[3][2], w3, hv2) FMA4(acc[3][3], w3, hv3)
        }

        float* rp = red + tid;   // column tid of each (g*4+b) row
#pragma unroll
        for (int g = 0; g < 4; g++)
#pragma unroll
            for (int b = 0; b < 4; b++)
                rp[(g * 4 + b) * 521] = acc[g][b];
        __syncthreads();

        // Finalize: every thread sums its 16 segments, activates its gate,
        // quad-shuffles to assemble (i,f,g,o), updates state redundantly.
        float s = gxv;
#pragma unroll
        for (int ks = 0; ks < 16; ks++)
            s += rbase[ks * 32];

        float sv = (gate == 2) ? 2.f * s : s;
        float e  = __expf(-sv);
        float v  = 1.f / (1.f + e);
        float a  = (gate == 2) ? (2.f * v - 1.f) : v;   // tanh for gate g, sigmoid else

        float ai = __shfl_sync(0xffffffffu, a, q + 0);
        float af = __shfl_sync(0xffffffffu, a, q + 1);
        float ag = __shfl_sync(0xffffffffu, a, q + 2);
        float ao = __shfl_sync(0xffffffffu, a, q + 3);

        float cn = af * c_reg + ai * ag;
        float hn = ao * tanhf(cn);
        c_reg = cn;

        if (gate == 0) {
            const int j = j0 + fjj;
            g_hbuf[(t + 1) & 1][fb * 512 + j] = hn;
            size_t off = (size_t)t * 16384 + (size_t)fb * 512 + j;
            out[OUT_OUTPUT + off] = hn;
            out[OUT_ALLH   + off] = hn;
            if (t == TT - 1) {
                out[OUT_HT + fb * 512 + j] = hn;
                out[OUT_CT + fb * 512 + j] = cn;
            }
        }

        // ---- grid barrier: parallel flag array + watcher broadcast ----
        if (t != TT - 1) {
            const unsigned int target = base + (unsigned)t + 1u;
            __syncthreads();   // all threads done with h_s / red of this step
            if (tid == 0) {
                __threadfence();                       // publish h/out writes
                *(volatile unsigned int*)&g_flags[bid * 32] = target;
            }
            if (bid == 0) {
                if (tid < 128) {
                    while (*(volatile unsigned int*)&g_flags[tid * 32] < target) { }
                }
                __syncthreads();
                if (tid == 0) {
                    __threadfence();
                    *(volatile unsigned int*)&g_gen = target;
                }
            } else {
                if (tid == 0) {
                    while (*(volatile unsigned int*)&g_gen < target) { }
                    __threadfence();                   // acquire
                }
                __syncthreads();
            }
        }
    }
}

// =========================================================================
extern "C" void kernel_launch(void* const* d_in, const int* in_sizes, int n_in,
                              void* d_out, int out_size)
{
    const float* x    = (const float*)d_in[0];
    const float* h0   = (const float*)d_in[1];
    const float* c0   = (const float*)d_in[2];
    const float* Wx   = (const float*)d_in[3];
    const float* Wh   = (const float*)d_in[4];
    const float* bias = (const float*)d_in[5];
    float* out = (float*)d_out;

    dim3 gridA(16, 256);           // N tiles x M tiles
    gemm_gx<<<gridA, 256>>>(x, Wx, bias);

    cudaFuncSetAttribute(lstm_seq, cudaFuncAttributeMaxDynamicSharedMemorySize, SMEM_BYTES);
    lstm_seq<<<128, 512, SMEM_BYTES>>>(h0, c0, Wh, out);
}